// round 1
// baseline (speedup 1.0000x reference)
#include <cuda_runtime.h>
#include <cstdint>

#define BB 8
#define TT 256
#define LL 48
#define FDIM 1024
#define WDIM 512
#define HD 512
#define OD 512
#define OUT_OFF (BB*TT*OD)                 /* 1048576 floats */
#define H2V_ELEMS (BB*TT*LL*HD)            /* 50331648 floats */

// ---------------- scratch (no allocations allowed) ----------------
__device__ float g_henc[BB*LL*HD];         // relu(word @ Ww + bw)
__device__ float g_v[BB*TT*HD];            // relu(frame @ Wf + bf)
__device__ float g_fww[BB*TT*HD];          // sum_l h2v * word

// ---------------- f32x2 helpers (Blackwell packed fp32) ----------------
__device__ __forceinline__ unsigned long long pack2(float a, float b) {
    unsigned long long r;
    asm("mov.b64 %0, {%1, %2};" : "=l"(r) : "f"(a), "f"(b));
    return r;
}
__device__ __forceinline__ void unpack2(unsigned long long p, float& lo, float& hi) {
    asm("mov.b64 {%0, %1}, %2;" : "=f"(lo), "=f"(hi) : "l"(p));
}
__device__ __forceinline__ void ffma2(unsigned long long& d,
                                      unsigned long long a, unsigned long long b) {
    asm("fma.rn.f32x2 %0, %1, %2, %0;" : "+l"(d) : "l"(a), "l"(b));
}
__device__ __forceinline__ float tanh_fast(float x) {
    float y; asm("tanh.approx.f32 %0, %1;" : "=f"(y) : "f"(x)); return y;
}

// ---------------- generic tiled GEMM: C = act(A[M,K] @ W[K,N] (+bias)) -------
// BM=BN=64, BK=16, 256 threads, 4x4 per-thread tile via f32x2 pairs along M.
// Requires M%64==0, N%64==0, K%16==0 (true for all 3 uses).
template<bool RELU, bool BIAS>
__global__ __launch_bounds__(256) void gemm_kernel(
    const float* __restrict__ A, const float* __restrict__ W,
    const float* __restrict__ bias, float* __restrict__ C,
    int M, int N, int K)
{
    __shared__ __align__(16) float As[16][68];   // [k][m], padded
    __shared__ __align__(16) float Bs[16][64];   // [k][n]
    const int tid = threadIdx.x;
    const int tx = tid & 15, ty = tid >> 4;
    const int m0 = blockIdx.y * 64, n0 = blockIdx.x * 64;

    unsigned long long acc[2][4] = {{0ull,0ull,0ull,0ull},{0ull,0ull,0ull,0ull}};

    for (int k0 = 0; k0 < K; k0 += 16) {
        {
            int r  = tid >> 2;            // 0..63 rows of A tile
            int k4 = (tid & 3) << 2;      // 0,4,8,12
            float4 a = *(const float4*)(A + (m0 + r) * K + k0 + k4);
            As[k4+0][r] = a.x; As[k4+1][r] = a.y;
            As[k4+2][r] = a.z; As[k4+3][r] = a.w;
            int kr = tid >> 4;            // 0..15
            int n4 = (tid & 15) << 2;     // 0..60
            *(float4*)&Bs[kr][n4] = *(const float4*)(W + (k0 + kr) * N + n0 + n4);
        }
        __syncthreads();
        #pragma unroll
        for (int kk = 0; kk < 16; ++kk) {
            ulonglong2 ap = *(const ulonglong2*)&As[kk][ty * 4];  // (m0,m1),(m2,m3)
            float4 bv = *(const float4*)&Bs[kk][tx * 4];
            unsigned long long bp0 = pack2(bv.x, bv.x);
            unsigned long long bp1 = pack2(bv.y, bv.y);
            unsigned long long bp2 = pack2(bv.z, bv.z);
            unsigned long long bp3 = pack2(bv.w, bv.w);
            ffma2(acc[0][0], ap.x, bp0); ffma2(acc[0][1], ap.x, bp1);
            ffma2(acc[0][2], ap.x, bp2); ffma2(acc[0][3], ap.x, bp3);
            ffma2(acc[1][0], ap.y, bp0); ffma2(acc[1][1], ap.y, bp1);
            ffma2(acc[1][2], ap.y, bp2); ffma2(acc[1][3], ap.y, bp3);
        }
        __syncthreads();
    }

    #pragma unroll
    for (int i2 = 0; i2 < 2; ++i2) {
        float lo[4], hi[4];
        #pragma unroll
        for (int j = 0; j < 4; ++j) unpack2(acc[i2][j], lo[j], hi[j]);
        int r0 = m0 + ty * 4 + i2 * 2;
        #pragma unroll
        for (int s = 0; s < 2; ++s) {
            float* vv = s ? hi : lo;
            float o0 = vv[0], o1 = vv[1], o2 = vv[2], o3 = vv[3];
            if (BIAS) {
                const float* bp = bias + n0 + tx * 4;
                o0 += bp[0]; o1 += bp[1]; o2 += bp[2]; o3 += bp[3];
            }
            if (RELU) {
                o0 = fmaxf(o0, 0.f); o1 = fmaxf(o1, 0.f);
                o2 = fmaxf(o2, 0.f); o3 = fmaxf(o3, 0.f);
            }
            float4 out4 = make_float4(o0, o1, o2, o3);
            *(float4*)(C + (r0 + s) * N + n0 + tx * 4) = out4;
        }
    }
}

// ---------------- fused attention kernel: one CTA per (b,t) ----------------
// S[h][l] = tanh(v[b,t,h] + henc[b,l,h]) in smem (transposed, k-major).
// R[l,h'] = relu(S^T @ Wa) computed in 4 chunks of 128 h' columns,
// then per-column softmax over l, h2v store, and fww accumulation.
// Templated on RI = ceil(wlen/16) rows-per-thread so masked-l work is skipped.

#define S_STRIDE 49
#define R_STRIDE 132
// smem floats: vt 512 | S 512*49 | Wt 32*128 | Rm 48*132
#define SMEM_FLOATS (512 + 512*S_STRIDE + 32*128 + LL*R_STRIDE)

template<int RI>
__device__ __forceinline__ void attn_body(
    int b, int t, int Lv,
    const float* __restrict__ Wa, const float* __restrict__ word,
    float* __restrict__ h2v,   // base for this (b,t), or nullptr
    float* vt, float* S, float* Wt, float* Rm)
{
    const int tid = threadIdx.x;
    const int th = tid & 15, tl = tid >> 4;
    const int R16 = RI * 16;

    // build S (k-major, padded stride 49); zero rows l in [Lv, R16)
    for (int idx = tid; idx < R16 * 512; idx += 256) {
        int l = idx >> 9, h = idx & 511;
        float s = 0.f;
        if (l < Lv) s = tanh_fast(vt[h] + g_henc[(b * LL + l) * HD + h]);
        S[h * S_STRIDE + l] = s;
    }

    for (int c = 0; c < 4; ++c) {
        unsigned long long acc[RI][4];
        #pragma unroll
        for (int i = 0; i < RI; ++i)
            #pragma unroll
            for (int j = 0; j < 4; ++j) acc[i][j] = 0ull;

        for (int k0 = 0; k0 < 512; k0 += 32) {
            __syncthreads();   // guards S build / prev-chunk Rm reads / prev Wt reads
            #pragma unroll
            for (int r = 0; r < 4; ++r) {
                int f  = tid + 256 * r;        // 0..1023 float4 slots
                int kr = f >> 5;
                int c4 = (f & 31) << 2;
                *(float4*)&Wt[kr * 128 + c4] =
                    *(const float4*)(Wa + (k0 + kr) * 512 + c * 128 + c4);
            }
            __syncthreads();
            #pragma unroll
            for (int kk = 0; kk < 32; ++kk) {
                ulonglong2 w0 = *(const ulonglong2*)&Wt[kk * 128 + th * 8];
                ulonglong2 w1 = *(const ulonglong2*)&Wt[kk * 128 + th * 8 + 4];
                #pragma unroll
                for (int i = 0; i < RI; ++i) {
                    float a = S[(k0 + kk) * S_STRIDE + tl + 16 * i];
                    unsigned long long ap = pack2(a, a);
                    ffma2(acc[i][0], ap, w0.x);
                    ffma2(acc[i][1], ap, w0.y);
                    ffma2(acc[i][2], ap, w1.x);
                    ffma2(acc[i][3], ap, w1.y);
                }
            }
        }

        // relu + stash R chunk to smem
        #pragma unroll
        for (int i = 0; i < RI; ++i) {
            int l = tl + 16 * i;
            #pragma unroll
            for (int j = 0; j < 4; ++j) {
                float lo, hi; unpack2(acc[i][j], lo, hi);
                Rm[l * R_STRIDE + th * 8 + 2 * j]     = fmaxf(lo, 0.f);
                Rm[l * R_STRIDE + th * 8 + 2 * j + 1] = fmaxf(hi, 0.f);
            }
        }
        __syncthreads();

        // per-column softmax over valid l + weighted sum with word_feats
        if (tid < 128) {
            int col = tid;
            int hg  = c * 128 + col;
            float mx = 0.f;   // relu outputs are >= 0 and Lv >= 1
            for (int l = 0; l < Lv; ++l) mx = fmaxf(mx, Rm[l * R_STRIDE + col]);
            float sum = 0.f;
            for (int l = 0; l < Lv; ++l) {
                float e = __expf(Rm[l * R_STRIDE + col] - mx);
                Rm[l * R_STRIDE + col] = e;
                sum += e;
            }
            float inv = 1.0f / sum;
            const float* wp = word + b * LL * WDIM + hg;
            float fww = 0.f;
            if (h2v) {
                float* hp = h2v + hg;
                for (int l = 0; l < Lv; ++l) {
                    float w = Rm[l * R_STRIDE + col] * inv;
                    hp[l * HD] = w;
                    fww += w * wp[l * WDIM];
                }
                for (int l = Lv; l < LL; ++l) hp[l * HD] = 0.f;
            } else {
                for (int l = 0; l < Lv; ++l)
                    fww += (Rm[l * R_STRIDE + col] * inv) * wp[l * WDIM];
            }
            g_fww[(b * TT + t) * HD + hg] = fww;
        }
        __syncthreads();
    }
}

__global__ __launch_bounds__(256, 1) void attn_kernel(
    const float* __restrict__ word, const int* __restrict__ flen,
    const int* __restrict__ wlen, const float* __restrict__ Wa,
    float* __restrict__ h2v_all, int write_h2v)
{
    const int t = blockIdx.x, b = blockIdx.y;
    extern __shared__ float sm[];
    float* vt = sm;
    float* S  = sm + 512;
    float* Wt = S + 512 * S_STRIDE;
    float* Rm = Wt + 32 * 128;

    float* h2v = write_h2v ? (h2v_all + (size_t)(b * TT + t) * LL * HD) : nullptr;
    const int fl = flen[b];

    if (t >= fl) {   // masked frame: h2v row and fww row are exactly zero
        float4 z = make_float4(0.f, 0.f, 0.f, 0.f);
        if (h2v) {
            float4* p = (float4*)h2v;
            for (int i = threadIdx.x; i < LL * HD / 4; i += 256) p[i] = z;
        }
        float4* q = (float4*)(g_fww + (size_t)(b * TT + t) * HD);
        for (int i = threadIdx.x; i < HD / 4; i += 256) q[i] = z;
        return;
    }

    int Lv = wlen[b];
    if (Lv > LL) Lv = LL;

    for (int h = threadIdx.x; h < 512; h += 256)
        vt[h] = g_v[(b * TT + t) * HD + h];
    __syncthreads();

    const int RI = (Lv + 15) >> 4;
    if (RI == 1)      attn_body<1>(b, t, Lv, Wa, word, h2v, vt, S, Wt, Rm);
    else if (RI == 2) attn_body<2>(b, t, Lv, Wa, word, h2v, vt, S, Wt, Rm);
    else              attn_body<3>(b, t, Lv, Wa, word, h2v, vt, S, Wt, Rm);
}

// ---------------- launcher ----------------
extern "C" void kernel_launch(void* const* d_in, const int* in_sizes, int n_in,
                              void* d_out, int out_size) {
    const float* frame = (const float*)d_in[0];
    const float* word  = (const float*)d_in[1];
    const int*   flen  = (const int*)  d_in[2];
    const int*   wlen  = (const int*)  d_in[3];
    const float* Wf    = (const float*)d_in[4];
    const float* bf    = (const float*)d_in[5];
    const float* Ww    = (const float*)d_in[6];
    const float* bw    = (const float*)d_in[7];
    const float* Wa    = (const float*)d_in[8];
    const float* Wout  = (const float*)d_in[9];
    float* out = (float*)d_out;

    float *henc, *v, *fww;
    cudaGetSymbolAddress((void**)&henc, g_henc);
    cudaGetSymbolAddress((void**)&v,    g_v);
    cudaGetSymbolAddress((void**)&fww,  g_fww);

    // 1) word encoder: henc = relu(word @ Ww + bw)   [384,512] K=512
    gemm_kernel<true, true><<<dim3(HD / 64, (BB * LL) / 64), 256>>>(
        word, Ww, bw, henc, BB * LL, HD, WDIM);

    // 2) frame encoder: v = relu(frame @ Wf + bf)    [2048,512] K=1024
    gemm_kernel<true, true><<<dim3(HD / 64, (BB * TT) / 64), 256>>>(
        frame, Wf, bf, v, BB * TT, HD, FDIM);

    // 3) fused tanh -> GEMM -> softmax -> weighted sum
    int write_h2v = (out_size >= OUT_OFF + H2V_ELEMS) ? 1 : 0;
    static const size_t smem_bytes = SMEM_FLOATS * sizeof(float);
    cudaFuncSetAttribute(attn_kernel,
                         cudaFuncAttributeMaxDynamicSharedMemorySize,
                         (int)smem_bytes);
    attn_kernel<<<dim3(TT, BB), 256, smem_bytes>>>(
        word, flen, wlen, Wa, out + OUT_OFF, write_h2v);

    // 4) out = fww @ Wout    [2048,512] K=512 (no bias, no relu)
    gemm_kernel<false, false><<<dim3(OD / 64, (BB * TT) / 64), 256>>>(
        fww, Wout, nullptr, out, BB * TT, OD, HD);
}

// round 4
// speedup vs baseline: 3.0326x; 3.0326x over previous
#include <cuda_runtime.h>
#include <cstdint>

#define BB 8
#define TT 256
#define LL 48
#define FDIM 1024
#define WDIM 512
#define HD 512
#define OD 512
#define OUT_OFF (BB*TT*OD)                 /* 1048576 floats */
#define H2V_ELEMS (BB*TT*LL*HD)            /* 50331648 floats */

// ---------------- scratch (no allocations allowed) ----------------
__device__ float g_henc[BB*LL*HD];         // relu(word @ Ww + bw)
__device__ float g_v[BB*TT*HD];            // relu(frame @ Wf + bf)
__device__ float g_fww[BB*TT*HD];          // sum_l h2v * word

// ---------------- helpers ----------------
__device__ __forceinline__ unsigned long long pack2(float a, float b) {
    unsigned long long r;
    asm("mov.b64 %0, {%1, %2};" : "=l"(r) : "f"(a), "f"(b));
    return r;
}
__device__ __forceinline__ void unpack2(unsigned long long p, float& lo, float& hi) {
    asm("mov.b64 {%0, %1}, %2;" : "=f"(lo), "=f"(hi) : "l"(p));
}
__device__ __forceinline__ void ffma2(unsigned long long& d,
                                      unsigned long long a, unsigned long long b) {
    asm("fma.rn.f32x2 %0, %1, %2, %0;" : "+l"(d) : "l"(a), "l"(b));
}
__device__ __forceinline__ float tanh_fast(float x) {
    float y; asm("tanh.approx.f32 %0, %1;" : "=f"(y) : "f"(x)); return y;
}
// tf32 cvt: destination must be a .b32 register ("=r"), NOT "=f"
__device__ __forceinline__ float to_tf32(float x) {
    uint32_t y; asm("cvt.rna.tf32.f32 %0, %1;" : "=r"(y) : "f"(x));
    return __uint_as_float(y);
}
__device__ __forceinline__ void mma_tf32(float* c, const uint32_t* a,
                                         uint32_t b0, uint32_t b1) {
    asm volatile("mma.sync.aligned.m16n8k8.row.col.f32.tf32.tf32.f32 "
                 "{%0,%1,%2,%3}, {%4,%5,%6,%7}, {%8,%9}, {%0,%1,%2,%3};"
                 : "+f"(c[0]), "+f"(c[1]), "+f"(c[2]), "+f"(c[3])
                 : "r"(a[0]), "r"(a[1]), "r"(a[2]), "r"(a[3]),
                   "r"(b0), "r"(b1));
}

// ---------------- generic tiled scalar GEMM (encoders + out) ----------------
template<bool RELU, bool BIAS>
__global__ __launch_bounds__(256) void gemm_kernel(
    const float* __restrict__ A, const float* __restrict__ W,
    const float* __restrict__ bias, float* __restrict__ C,
    int M, int N, int K)
{
    __shared__ __align__(16) float As[16][68];
    __shared__ __align__(16) float Bs[16][64];
    const int tid = threadIdx.x;
    const int tx = tid & 15, ty = tid >> 4;
    const int m0 = blockIdx.y * 64, n0 = blockIdx.x * 64;

    unsigned long long acc[2][4] = {{0ull,0ull,0ull,0ull},{0ull,0ull,0ull,0ull}};

    for (int k0 = 0; k0 < K; k0 += 16) {
        {
            int r  = tid >> 2;
            int k4 = (tid & 3) << 2;
            float4 a = *(const float4*)(A + (m0 + r) * K + k0 + k4);
            As[k4+0][r] = a.x; As[k4+1][r] = a.y;
            As[k4+2][r] = a.z; As[k4+3][r] = a.w;
            int kr = tid >> 4;
            int n4 = (tid & 15) << 2;
            *(float4*)&Bs[kr][n4] = *(const float4*)(W + (k0 + kr) * N + n0 + n4);
        }
        __syncthreads();
        #pragma unroll
        for (int kk = 0; kk < 16; ++kk) {
            ulonglong2 ap = *(const ulonglong2*)&As[kk][ty * 4];
            float4 bv = *(const float4*)&Bs[kk][tx * 4];
            unsigned long long bp0 = pack2(bv.x, bv.x);
            unsigned long long bp1 = pack2(bv.y, bv.y);
            unsigned long long bp2 = pack2(bv.z, bv.z);
            unsigned long long bp3 = pack2(bv.w, bv.w);
            ffma2(acc[0][0], ap.x, bp0); ffma2(acc[0][1], ap.x, bp1);
            ffma2(acc[0][2], ap.x, bp2); ffma2(acc[0][3], ap.x, bp3);
            ffma2(acc[1][0], ap.y, bp0); ffma2(acc[1][1], ap.y, bp1);
            ffma2(acc[1][2], ap.y, bp2); ffma2(acc[1][3], ap.y, bp3);
        }
        __syncthreads();
    }

    #pragma unroll
    for (int i2 = 0; i2 < 2; ++i2) {
        float lo[4], hi[4];
        #pragma unroll
        for (int j = 0; j < 4; ++j) unpack2(acc[i2][j], lo[j], hi[j]);
        int r0 = m0 + ty * 4 + i2 * 2;
        #pragma unroll
        for (int s = 0; s < 2; ++s) {
            float* vv = s ? hi : lo;
            float o0 = vv[0], o1 = vv[1], o2 = vv[2], o3 = vv[3];
            if (BIAS) {
                const float* bp = bias + n0 + tx * 4;
                o0 += bp[0]; o1 += bp[1]; o2 += bp[2]; o3 += bp[3];
            }
            if (RELU) {
                o0 = fmaxf(o0, 0.f); o1 = fmaxf(o1, 0.f);
                o2 = fmaxf(o2, 0.f); o3 = fmaxf(o3, 0.f);
            }
            *(float4*)(C + (r0 + s) * N + n0 + tx * 4) = make_float4(o0, o1, o2, o3);
        }
    }
}

// ---------------- fused attention via mma.sync tf32 ----------------
// CTA: 128 rows (TPB t's x Lp l-slots) x 128 cols (n-block), K=512.
// A built in-kernel: tanh(v[t] + henc[l]) -> tf32. B = Wa chunk -> tf32.
// Epilogue: relu -> per-(t,col) softmax over l -> h2v + fww.

#define AS_STR 36
#define BS_STR 132
#define R_STR2 132

#define OFF_HENC 0                         /* 48*512*4  = 98304, reused as R  */
#define OFF_VT   98304                     /* 8*512*4   = 16384 */
#define OFF_AS   114688                    /* 2*128*36*4 = 36864 */
#define OFF_BS   151552                    /* 2*32*132*4 = 33792 */
#define SMEM_TOTAL_ATT 185344

__global__ __launch_bounds__(256, 1) void attn_mma2(
    const float* __restrict__ Wa, const float* __restrict__ word,
    const int* __restrict__ flen, const int* __restrict__ wlen,
    float* __restrict__ h2v_all, int write_h2v)
{
    extern __shared__ char smem[];
    const int tid = threadIdx.x;
    const int b  = blockIdx.y >> 7;
    const int yl = blockIdx.y & 127;
    const int n0 = blockIdx.x * 128;
    const int fl = flen[b];

    int Lv = wlen[b]; if (Lv > LL) Lv = LL;
    const int lpsh = (Lv <= 16) ? 4 : (Lv <= 32) ? 5 : 6;
    const int lpmask = (1 << lpsh) - 1;
    const int TPB = 128 >> lpsh;
    const int t0 = yl * TPB;
    if (t0 >= TT) return;

    float* h2v = write_h2v ? h2v_all : nullptr;

    if (t0 >= fl) {
        if (h2v) {
            for (int i = tid; i < TPB * LL * 32; i += 256) {
                int t = i / (LL * 32);
                int rem = i - t * (LL * 32);
                int l = rem >> 5, c4 = (rem & 31) << 2;
                *(float4*)&h2v[(((size_t)(b * TT + t0 + t) * LL + l) * HD) + n0 + c4] =
                    make_float4(0.f, 0.f, 0.f, 0.f);
            }
        }
        for (int i = tid; i < TPB * 32; i += 256) {
            int t = i >> 5, c4 = (i & 31) << 2;
            *(float4*)&g_fww[(size_t)(b * TT + t0 + t) * HD + n0 + c4] =
                make_float4(0.f, 0.f, 0.f, 0.f);
        }
        return;
    }

    float* hencS = (float*)(smem + OFF_HENC);
    float* vt    = (float*)(smem + OFF_VT);
    float* R     = (float*)(smem + OFF_HENC);   // reused after GEMM

    for (int i = tid; i < Lv * 128; i += 256) {
        int l = i >> 7, c4 = (i & 127) << 2;
        *(float4*)&hencS[l * 512 + c4] =
            *(const float4*)&g_henc[((size_t)(b * LL + l)) * HD + c4];
    }
    for (int i = tid; i < TPB * 128; i += 256) {
        int t = i >> 7, c4 = (i & 127) << 2;
        *(float4*)&vt[t * 512 + c4] =
            *(const float4*)&g_v[((size_t)(b * TT + t0 + t)) * HD + c4];
    }
    __syncthreads();

    const int lane = tid & 31;
    const int wid  = tid >> 5;
    const int g    = lane >> 2;        // group id (row within frag)
    const int tig  = lane & 3;         // thread-in-group (k / col pair)
    const int wm   = wid & 3;
    const int wn   = wid >> 2;
    const int warp_m0 = wm * 32;
    const int warp_n0 = wn * 64;

    float c[2][8][4];
    #pragma unroll
    for (int mi = 0; mi < 2; ++mi)
        #pragma unroll
        for (int nf = 0; nf < 8; ++nf)
            #pragma unroll
            for (int j = 0; j < 4; ++j) c[mi][nf][j] = 0.f;

    auto build_chunk = [&](int gch, int bufsel) {
        const int k0 = gch * 32;
        float* As = (float*)(smem + OFF_AS) + bufsel * (128 * AS_STR);
        float* Bs = (float*)(smem + OFF_BS) + bufsel * (32 * BS_STR);
        // A: 128 rows x 32 k  (1024 float4 tasks)
        for (int i = tid; i < 1024; i += 256) {
            int r = i >> 3, kq = i & 7;
            int tl = r >> lpsh, l = r & lpmask;
            float4 val = make_float4(0.f, 0.f, 0.f, 0.f);
            if (l < Lv) {
                int kk = k0 + kq * 4;
                float4 hv = *(const float4*)&hencS[l * 512 + kk];
                const float* vp = &vt[tl * 512 + kk];
                val.x = to_tf32(tanh_fast(vp[0] + hv.x));
                val.y = to_tf32(tanh_fast(vp[1] + hv.y));
                val.z = to_tf32(tanh_fast(vp[2] + hv.z));
                val.w = to_tf32(tanh_fast(vp[3] + hv.w));
            }
            *(float4*)&As[r * AS_STR + kq * 4] = val;
        }
        // B: 32 k x 128 n  (1024 float4 tasks)
        for (int i = tid; i < 1024; i += 256) {
            int kk = i >> 5, nq = (i & 31) << 2;
            float4 wv = *(const float4*)&Wa[(size_t)(k0 + kk) * HD + n0 + nq];
            wv.x = to_tf32(wv.x); wv.y = to_tf32(wv.y);
            wv.z = to_tf32(wv.z); wv.w = to_tf32(wv.w);
            *(float4*)&Bs[kk * BS_STR + nq] = wv;
        }
    };

    auto mma_chunk = [&](int bufsel) {
        const float* As = (float*)(smem + OFF_AS) + bufsel * (128 * AS_STR);
        const float* Bs = (float*)(smem + OFF_BS) + bufsel * (32 * BS_STR);
        #pragma unroll
        for (int ks = 0; ks < 4; ++ks) {
            const int kk = ks * 8;
            uint32_t a[2][4];
            #pragma unroll
            for (int mi = 0; mi < 2; ++mi) {
                int r0 = warp_m0 + mi * 16;
                a[mi][0] = __float_as_uint(As[(r0 + g)     * AS_STR + kk + tig]);
                a[mi][1] = __float_as_uint(As[(r0 + 8 + g) * AS_STR + kk + tig]);
                a[mi][2] = __float_as_uint(As[(r0 + g)     * AS_STR + kk + tig + 4]);
                a[mi][3] = __float_as_uint(As[(r0 + 8 + g) * AS_STR + kk + tig + 4]);
            }
            #pragma unroll
            for (int nf = 0; nf < 8; ++nf) {
                int cc = warp_n0 + nf * 8 + g;
                uint32_t b0 = __float_as_uint(Bs[(kk + tig)     * BS_STR + cc]);
                uint32_t b1 = __float_as_uint(Bs[(kk + tig + 4) * BS_STR + cc]);
                mma_tf32(c[0][nf], a[0], b0, b1);
                mma_tf32(c[1][nf], a[1], b0, b1);
            }
        }
    };

    build_chunk(0, 0);
    __syncthreads();
    for (int gch = 0; gch < 16; ++gch) {
        if (gch < 15) build_chunk(gch + 1, (gch + 1) & 1);
        mma_chunk(gch & 1);
        __syncthreads();
    }

    // write relu(C) into R [128][132]
    #pragma unroll
    for (int mi = 0; mi < 2; ++mi) {
        #pragma unroll
        for (int nf = 0; nf < 8; ++nf) {
            int rr0 = warp_m0 + mi * 16 + g;
            int cc  = warp_n0 + nf * 8 + tig * 2;
            float2 lo = make_float2(fmaxf(c[mi][nf][0], 0.f), fmaxf(c[mi][nf][1], 0.f));
            float2 hi = make_float2(fmaxf(c[mi][nf][2], 0.f), fmaxf(c[mi][nf][3], 0.f));
            *(float2*)&R[rr0 * R_STR2 + cc]       = lo;
            *(float2*)&R[(rr0 + 8) * R_STR2 + cc] = hi;
        }
    }
    __syncthreads();

    // softmax over l + h2v + fww
    const int col  = tid & 127;
    const int half = tid >> 7;
    for (int tg = half; tg < TPB; tg += 2) {
        const int t = t0 + tg;
        const int rb = tg << lpsh;
        const int hg = n0 + col;
        float* hp = h2v ? (h2v + ((size_t)(b * TT + t) * LL) * HD + hg) : nullptr;
        if (t < fl) {
            float mx = 0.f;
            for (int l = 0; l < Lv; ++l)
                mx = fmaxf(mx, R[(rb + l) * R_STR2 + col]);
            float sum = 0.f;
            for (int l = 0; l < Lv; ++l) {
                float e = __expf(R[(rb + l) * R_STR2 + col] - mx);
                R[(rb + l) * R_STR2 + col] = e;
                sum += e;
            }
            float inv = 1.0f / sum;
            const float* wp = word + ((size_t)b * LL) * WDIM + hg;
            float fww = 0.f;
            for (int l = 0; l < Lv; ++l) {
                float w = R[(rb + l) * R_STR2 + col] * inv;
                if (hp) hp[(size_t)l * HD] = w;
                fww += w * wp[(size_t)l * WDIM];
            }
            if (hp)
                for (int l = Lv; l < LL; ++l) hp[(size_t)l * HD] = 0.f;
            g_fww[(size_t)(b * TT + t) * HD + hg] = fww;
        } else {
            if (hp)
                for (int l = 0; l < LL; ++l) hp[(size_t)l * HD] = 0.f;
            g_fww[(size_t)(b * TT + t) * HD + hg] = 0.f;
        }
    }
}

// ---------------- launcher ----------------
extern "C" void kernel_launch(void* const* d_in, const int* in_sizes, int n_in,
                              void* d_out, int out_size) {
    const float* frame = (const float*)d_in[0];
    const float* word  = (const float*)d_in[1];
    const int*   flen  = (const int*)  d_in[2];
    const int*   wlen  = (const int*)  d_in[3];
    const float* Wf    = (const float*)d_in[4];
    const float* bf    = (const float*)d_in[5];
    const float* Ww    = (const float*)d_in[6];
    const float* bw    = (const float*)d_in[7];
    const float* Wa    = (const float*)d_in[8];
    const float* Wout  = (const float*)d_in[9];
    float* out = (float*)d_out;

    float *henc, *v, *fww;
    cudaGetSymbolAddress((void**)&henc, g_henc);
    cudaGetSymbolAddress((void**)&v,    g_v);
    cudaGetSymbolAddress((void**)&fww,  g_fww);

    // 1) word encoder: henc = relu(word @ Ww + bw)
    gemm_kernel<true, true><<<dim3(HD / 64, (BB * LL) / 64), 256>>>(
        word, Ww, bw, henc, BB * LL, HD, WDIM);

    // 2) frame encoder: v = relu(frame @ Wf + bf)
    gemm_kernel<true, true><<<dim3(HD / 64, (BB * TT) / 64), 256>>>(
        frame, Wf, bf, v, BB * TT, HD, FDIM);

    // 3) fused attention (mma.sync tf32)
    int write_h2v = (out_size >= OUT_OFF + H2V_ELEMS) ? 1 : 0;
    cudaFuncSetAttribute(attn_mma2,
                         cudaFuncAttributeMaxDynamicSharedMemorySize, SMEM_TOTAL_ATT);
    attn_mma2<<<dim3(4, BB * 128), 256, SMEM_TOTAL_ATT>>>(
        Wa, word, flen, wlen, out + OUT_OFF, write_h2v);

    // 4) out = fww @ Wout
    gemm_kernel<false, false><<<dim3(OD / 64, (BB * TT) / 64), 256>>>(
        fww, Wout, nullptr, out, BB * TT, OD, HD);
}

// round 5
// speedup vs baseline: 3.1223x; 1.0296x over previous
#include <cuda_runtime.h>
#include <cstdint>

#define BB 8
#define TT 256
#define LL 48
#define FDIM 1024
#define WDIM 512
#define HD 512
#define OD 512
#define OUT_OFF (BB*TT*OD)                 /* 1048576 floats */
#define H2V_ELEMS (BB*TT*LL*HD)            /* 50331648 floats */

// ---------------- scratch (no allocations allowed) ----------------
__device__ float g_henc[BB*LL*HD];         // relu(word @ Ww + bw)
__device__ float g_v[BB*TT*HD];            // relu(frame @ Wf + bf)
__device__ float g_fww[BB*TT*HD];          // sum_l h2v * word

// ---------------- helpers ----------------
__device__ __forceinline__ float tanh_fast(float x) {
    float y; asm("tanh.approx.f32 %0, %1;" : "=f"(y) : "f"(x)); return y;
}
// tf32 cvt: destination must be a .b32 register
__device__ __forceinline__ float to_tf32(float x) {
    uint32_t y; asm("cvt.rna.tf32.f32 %0, %1;" : "=r"(y) : "f"(x));
    return __uint_as_float(y);
}
__device__ __forceinline__ void mma_tf32(float* c, const uint32_t* a,
                                         uint32_t b0, uint32_t b1) {
    asm volatile("mma.sync.aligned.m16n8k8.row.col.f32.tf32.tf32.f32 "
                 "{%0,%1,%2,%3}, {%4,%5,%6,%7}, {%8,%9}, {%0,%1,%2,%3};"
                 : "+f"(c[0]), "+f"(c[1]), "+f"(c[2]), "+f"(c[3])
                 : "r"(a[0]), "r"(a[1]), "r"(a[2]), "r"(a[3]),
                   "r"(b0), "r"(b1));
}

// ================= tensor-core GEMM for encoders / out =================
// Tile 128x128, K chunks of 32, double-buffered. 256 threads, 8 warps (4m x 2n),
// warp tile 32x64. C = act(A[M,K] @ W[K,N] (+bias)). M%128==0, N%128==0, K%32==0.
#define GT_AS (128*36)
#define GT_BS (32*132)
#define GT_SMEM ((2*GT_AS + 2*GT_BS)*4)    /* 70656 bytes */

template<bool RELU, bool BIAS>
__global__ __launch_bounds__(256) void gemm_tc(
    const float* __restrict__ A, const float* __restrict__ W,
    const float* __restrict__ bias, float* __restrict__ C,
    int M, int N, int K)
{
    extern __shared__ float sm[];
    float* As = sm;
    float* Bs = sm + 2*GT_AS;
    const int tid = threadIdx.x;
    const int m0 = blockIdx.y * 128, n0 = blockIdx.x * 128;

    const int lane = tid & 31, wid = tid >> 5;
    const int g = lane >> 2, tig = lane & 3;
    const int wm = wid & 3, wn = wid >> 2;
    const int warp_m0 = wm * 32, warp_n0 = wn * 64;

    float c[2][8][4];
    #pragma unroll
    for (int mi = 0; mi < 2; ++mi)
        #pragma unroll
        for (int nf = 0; nf < 8; ++nf)
            #pragma unroll
            for (int j = 0; j < 4; ++j) c[mi][nf][j] = 0.f;

    auto build = [&](int k0, int bsel) {
        float* as = As + bsel * GT_AS;
        float* bs = Bs + bsel * GT_BS;
        #pragma unroll
        for (int ii = 0; ii < 4; ++ii) {
            int i = tid + ii * 256;
            int r = i >> 3, kq = (i & 7) << 2;
            float4 av = *(const float4*)(A + (size_t)(m0 + r) * K + k0 + kq);
            av.x = to_tf32(av.x); av.y = to_tf32(av.y);
            av.z = to_tf32(av.z); av.w = to_tf32(av.w);
            *(float4*)&as[r * 36 + kq] = av;
        }
        #pragma unroll
        for (int ii = 0; ii < 4; ++ii) {
            int i = tid + ii * 256;
            int kk = i >> 5, nq = (i & 31) << 2;
            float4 wv = *(const float4*)(W + (size_t)(k0 + kk) * N + n0 + nq);
            wv.x = to_tf32(wv.x); wv.y = to_tf32(wv.y);
            wv.z = to_tf32(wv.z); wv.w = to_tf32(wv.w);
            *(float4*)&bs[kk * 132 + nq] = wv;
        }
    };

    build(0, 0);
    __syncthreads();
    const int nch = K >> 5;
    for (int gch = 0; gch < nch; ++gch) {
        if (gch + 1 < nch) build((gch + 1) << 5, (gch + 1) & 1);
        const float* as = As + (gch & 1) * GT_AS;
        const float* bs = Bs + (gch & 1) * GT_BS;
        #pragma unroll
        for (int ks = 0; ks < 4; ++ks) {
            const int kk = ks * 8;
            uint32_t a[2][4];
            #pragma unroll
            for (int mi = 0; mi < 2; ++mi) {
                int r0 = warp_m0 + mi * 16;
                a[mi][0] = __float_as_uint(as[(r0 + g)     * 36 + kk + tig]);
                a[mi][1] = __float_as_uint(as[(r0 + 8 + g) * 36 + kk + tig]);
                a[mi][2] = __float_as_uint(as[(r0 + g)     * 36 + kk + tig + 4]);
                a[mi][3] = __float_as_uint(as[(r0 + 8 + g) * 36 + kk + tig + 4]);
            }
            #pragma unroll
            for (int nf = 0; nf < 8; ++nf) {
                int cc = warp_n0 + nf * 8 + g;
                uint32_t b0 = __float_as_uint(bs[(kk + tig)     * 132 + cc]);
                uint32_t b1 = __float_as_uint(bs[(kk + tig + 4) * 132 + cc]);
                mma_tf32(c[0][nf], a[0], b0, b1);
                mma_tf32(c[1][nf], a[1], b0, b1);
            }
        }
        __syncthreads();
    }

    // epilogue: bias + relu + direct store
    #pragma unroll
    for (int mi = 0; mi < 2; ++mi) {
        #pragma unroll
        for (int nf = 0; nf < 8; ++nf) {
            int r0 = m0 + warp_m0 + mi * 16 + g;
            int cc = n0 + warp_n0 + nf * 8 + tig * 2;
            float o0 = c[mi][nf][0], o1 = c[mi][nf][1];
            float o2 = c[mi][nf][2], o3 = c[mi][nf][3];
            if (BIAS) {
                float bb0 = bias[cc], bb1 = bias[cc + 1];
                o0 += bb0; o1 += bb1; o2 += bb0; o3 += bb1;
            }
            if (RELU) {
                o0 = fmaxf(o0, 0.f); o1 = fmaxf(o1, 0.f);
                o2 = fmaxf(o2, 0.f); o3 = fmaxf(o3, 0.f);
            }
            *(float2*)(C + (size_t)r0 * N + cc)       = make_float2(o0, o1);
            *(float2*)(C + (size_t)(r0 + 8) * N + cc) = make_float2(o2, o3);
        }
    }
}

// ================= fused attention v3 =================
// One CTA: 64 rows (TPB t's x Lp l-slots) x ALL 512 cols.
// A = tf32(tanh(v+henc)) built ONCE into persistent smem (64x516),
// then 4 n-passes of 128 cols: MMA (K=512, 32-chunks double-buffered B),
// relu -> R -> per-(t,col) softmax over l -> h2v + fww.
#define AT_A  0                     /* 64*516 = 33024 floats */
#define AT_B  33024                 /* 2*32*132 = 8448 */
#define AT_R  41472                 /* 64*132  = 8448 */
#define AT_VT 49920                 /* 4*512   = 2048 */
#define AT_SMEM ((49920 + 2048) * 4)   /* 207872 bytes */

__global__ __launch_bounds__(256, 1) void attn_v3(
    const float* __restrict__ Wa, const float* __restrict__ word,
    const int* __restrict__ flen, const int* __restrict__ wlen,
    float* __restrict__ h2v_all, int write_h2v)
{
    extern __shared__ float sm[];
    const int tid = threadIdx.x;
    const int b  = blockIdx.y >> 8;
    const int yl = blockIdx.y & 255;
    const int fl = flen[b];

    int Lv = wlen[b]; if (Lv > LL) Lv = LL;
    const int lpsh = (Lv <= 16) ? 4 : (Lv <= 32) ? 5 : 6;
    const int lpmask = (1 << lpsh) - 1;
    const int TPB = 64 >> lpsh;                // 4 / 2 / 1
    const int t0 = yl * TPB;
    if (t0 >= TT) return;

    float* h2v = write_h2v ? h2v_all : nullptr;

    if (t0 >= fl) {       // fully masked t's: exact zeros
        float4 z = make_float4(0.f, 0.f, 0.f, 0.f);
        if (h2v) {
            for (int i = tid; i < TPB * LL * 128; i += 256) {
                int t = i / (LL * 128);
                int rem = i - t * (LL * 128);
                int l = rem >> 7, c4 = (rem & 127) << 2;
                *(float4*)&h2v[((size_t)(b * TT + t0 + t) * LL + l) * HD + c4] = z;
            }
        }
        for (int i = tid; i < TPB * 128; i += 256) {
            int t = i >> 7, c4 = (i & 127) << 2;
            *(float4*)&g_fww[(size_t)(b * TT + t0 + t) * HD + c4] = z;
        }
        return;
    }

    float* Am = sm + AT_A;
    float* Bb = sm + AT_B;
    float* R  = sm + AT_R;
    float* vt = sm + AT_VT;

    // stage v rows
    for (int i = tid; i < TPB * 128; i += 256) {
        int tl = i >> 7, c4 = (i & 127) << 2;
        *(float4*)&vt[tl * 512 + c4] =
            *(const float4*)&g_v[(size_t)(b * TT + t0 + tl) * HD + c4];
    }
    __syncthreads();

    // build A ONCE: tanh(v + henc) -> tf32, rows (t,l), zero padded l
    for (int i = tid; i < 64 * 128; i += 256) {
        int r = i >> 7, c4 = (i & 127) << 2;
        int tl = r >> lpsh, l = r & lpmask;
        float4 val = make_float4(0.f, 0.f, 0.f, 0.f);
        if (l < Lv) {
            float4 hv = *(const float4*)&g_henc[(size_t)(b * LL + l) * HD + c4];
            const float* vp = &vt[tl * 512 + c4];
            val.x = to_tf32(tanh_fast(vp[0] + hv.x));
            val.y = to_tf32(tanh_fast(vp[1] + hv.y));
            val.z = to_tf32(tanh_fast(vp[2] + hv.z));
            val.w = to_tf32(tanh_fast(vp[3] + hv.w));
        }
        *(float4*)&Am[r * 516 + c4] = val;
    }
    __syncthreads();

    const int lane = tid & 31, wid = tid >> 5;
    const int g = lane >> 2, tig = lane & 3;
    const int wm = wid & 1, wn = wid >> 1;      // 2m x 4n warp grid
    const int warp_m0 = wm * 32, warp_n0 = wn * 32;

    for (int pass = 0; pass < 4; ++pass) {
        const int n0p = pass * 128;

        float c[2][4][4];
        #pragma unroll
        for (int mi = 0; mi < 2; ++mi)
            #pragma unroll
            for (int nf = 0; nf < 4; ++nf)
                #pragma unroll
                for (int j = 0; j < 4; ++j) c[mi][nf][j] = 0.f;

        auto buildB = [&](int gch, int bsel) {
            const int k0 = gch << 5;
            float* bs = Bb + bsel * (32 * 132);
            #pragma unroll
            for (int ii = 0; ii < 4; ++ii) {
                int i = tid + ii * 256;
                int kk = i >> 5, nq = (i & 31) << 2;
                float4 wv = *(const float4*)&Wa[(size_t)(k0 + kk) * HD + n0p + nq];
                wv.x = to_tf32(wv.x); wv.y = to_tf32(wv.y);
                wv.z = to_tf32(wv.z); wv.w = to_tf32(wv.w);
                *(float4*)&bs[kk * 132 + nq] = wv;
            }
        };

        buildB(0, 0);
        __syncthreads();
        for (int gch = 0; gch < 16; ++gch) {
            if (gch < 15) buildB(gch + 1, (gch + 1) & 1);
            const float* bs = Bb + (gch & 1) * (32 * 132);
            const int kof = gch << 5;
            #pragma unroll
            for (int ks = 0; ks < 4; ++ks) {
                const int kk = kof + ks * 8;
                uint32_t a[2][4];
                #pragma unroll
                for (int mi = 0; mi < 2; ++mi) {
                    int r0 = warp_m0 + mi * 16;
                    a[mi][0] = __float_as_uint(Am[(r0 + g)     * 516 + kk + tig]);
                    a[mi][1] = __float_as_uint(Am[(r0 + 8 + g) * 516 + kk + tig]);
                    a[mi][2] = __float_as_uint(Am[(r0 + g)     * 516 + kk + tig + 4]);
                    a[mi][3] = __float_as_uint(Am[(r0 + 8 + g) * 516 + kk + tig + 4]);
                }
                const int kl = ks * 8;
                #pragma unroll
                for (int nf = 0; nf < 4; ++nf) {
                    int cc = warp_n0 + nf * 8 + g;
                    uint32_t b0 = __float_as_uint(bs[(kl + tig)     * 132 + cc]);
                    uint32_t b1 = __float_as_uint(bs[(kl + tig + 4) * 132 + cc]);
                    mma_tf32(c[0][nf], a[0], b0, b1);
                    mma_tf32(c[1][nf], a[1], b0, b1);
                }
            }
            __syncthreads();
        }

        // relu(C) -> R [64][132]
        #pragma unroll
        for (int mi = 0; mi < 2; ++mi) {
            #pragma unroll
            for (int nf = 0; nf < 4; ++nf) {
                int rr0 = warp_m0 + mi * 16 + g;
                int cc  = warp_n0 + nf * 8 + tig * 2;
                *(float2*)&R[rr0 * 132 + cc] =
                    make_float2(fmaxf(c[mi][nf][0], 0.f), fmaxf(c[mi][nf][1], 0.f));
                *(float2*)&R[(rr0 + 8) * 132 + cc] =
                    make_float2(fmaxf(c[mi][nf][2], 0.f), fmaxf(c[mi][nf][3], 0.f));
            }
        }
        __syncthreads();

        // softmax over l + h2v + fww for cols [n0p, n0p+128)
        const int col = tid & 127;
        const int half = tid >> 7;
        for (int tg = half; tg < TPB; tg += 2) {
            const int t = t0 + tg;
            const int rb = tg << lpsh;
            const int hg = n0p + col;
            float* hp = h2v ? (h2v + ((size_t)(b * TT + t) * LL) * HD + hg) : nullptr;
            if (t < fl) {
                float mx = 0.f;
                for (int l = 0; l < Lv; ++l)
                    mx = fmaxf(mx, R[(rb + l) * 132 + col]);
                float sum = 0.f;
                for (int l = 0; l < Lv; ++l) {
                    float e = __expf(R[(rb + l) * 132 + col] - mx);
                    R[(rb + l) * 132 + col] = e;
                    sum += e;
                }
                float inv = 1.0f / sum;
                const float* wp = word + ((size_t)b * LL) * WDIM + hg;
                float fww = 0.f;
                for (int l = 0; l < Lv; ++l) {
                    float w = R[(rb + l) * 132 + col] * inv;
                    if (hp) hp[(size_t)l * HD] = w;
                    fww += w * wp[(size_t)l * WDIM];
                }
                if (hp)
                    for (int l = Lv; l < LL; ++l) hp[(size_t)l * HD] = 0.f;
                g_fww[(size_t)(b * TT + t) * HD + hg] = fww;
            } else {
                if (hp)
                    for (int l = 0; l < LL; ++l) hp[(size_t)l * HD] = 0.f;
                g_fww[(size_t)(b * TT + t) * HD + hg] = 0.f;
            }
        }
        __syncthreads();
    }
}

// ---------------- launcher ----------------
extern "C" void kernel_launch(void* const* d_in, const int* in_sizes, int n_in,
                              void* d_out, int out_size) {
    const float* frame = (const float*)d_in[0];
    const float* word  = (const float*)d_in[1];
    const int*   flen  = (const int*)  d_in[2];
    const int*   wlen  = (const int*)  d_in[3];
    const float* Wf    = (const float*)d_in[4];
    const float* bf    = (const float*)d_in[5];
    const float* Ww    = (const float*)d_in[6];
    const float* bw    = (const float*)d_in[7];
    const float* Wa    = (const float*)d_in[8];
    const float* Wout  = (const float*)d_in[9];
    float* out = (float*)d_out;

    float *henc, *v, *fww;
    cudaGetSymbolAddress((void**)&henc, g_henc);
    cudaGetSymbolAddress((void**)&v,    g_v);
    cudaGetSymbolAddress((void**)&fww,  g_fww);

    cudaFuncSetAttribute(gemm_tc<true, true>,
                         cudaFuncAttributeMaxDynamicSharedMemorySize, GT_SMEM);
    cudaFuncSetAttribute(gemm_tc<false, false>,
                         cudaFuncAttributeMaxDynamicSharedMemorySize, GT_SMEM);
    cudaFuncSetAttribute(attn_v3,
                         cudaFuncAttributeMaxDynamicSharedMemorySize, AT_SMEM);

    // 1) word encoder: henc = relu(word @ Ww + bw)   [384,512] K=512
    gemm_tc<true, true><<<dim3(HD / 128, (BB * LL) / 128), 256, GT_SMEM>>>(
        word, Ww, bw, henc, BB * LL, HD, WDIM);

    // 2) frame encoder: v = relu(frame @ Wf + bf)    [2048,512] K=1024
    gemm_tc<true, true><<<dim3(HD / 128, (BB * TT) / 128), 256, GT_SMEM>>>(
        frame, Wf, bf, v, BB * TT, HD, FDIM);

    // 3) fused attention (mma.sync tf32, A built once per CTA)
    int write_h2v = (out_size >= OUT_OFF + H2V_ELEMS) ? 1 : 0;
    attn_v3<<<dim3(1, BB * 256), 256, AT_SMEM>>>(
        Wa, word, flen, wlen, out + OUT_OFF, write_h2v);

    // 4) out = fww @ Wout    [2048,512] K=512
    gemm_tc<false, false><<<dim3(OD / 128, (BB * TT) / 128), 256, GT_SMEM>>>(
        fww, Wout, nullptr, out, BB * TT, OD, HD);
}

// round 6
// speedup vs baseline: 4.3438x; 1.3912x over previous
#include <cuda_runtime.h>
#include <cstdint>

#define BB 8
#define TT 256
#define LL 48
#define FDIM 1024
#define WDIM 512
#define HD 512
#define OD 512
#define OUT_OFF (BB*TT*OD)                 /* 1048576 floats */
#define H2V_ELEMS (BB*TT*LL*HD)            /* 50331648 floats */

// ---------------- scratch (no allocations allowed) ----------------
__device__ float g_henc[BB*LL*HD];         // relu(word @ Ww + bw)
__device__ float g_v[BB*TT*HD];            // relu(frame @ Wf + bf)
__device__ float g_fww[BB*TT*HD];          // sum_l h2v * word

// ---------------- helpers ----------------
__device__ __forceinline__ float tanh_fast(float x) {
    float y; asm("tanh.approx.f32 %0, %1;" : "=f"(y) : "f"(x)); return y;
}
__device__ __forceinline__ float to_tf32(float x) {
    uint32_t y; asm("cvt.rna.tf32.f32 %0, %1;" : "=r"(y) : "f"(x));
    return __uint_as_float(y);
}
__device__ __forceinline__ float4 cvt4(float4 v) {
    v.x = to_tf32(v.x); v.y = to_tf32(v.y);
    v.z = to_tf32(v.z); v.w = to_tf32(v.w);
    return v;
}
__device__ __forceinline__ void mma_tf32(float* c, const uint32_t* a,
                                         uint32_t b0, uint32_t b1) {
    asm volatile("mma.sync.aligned.m16n8k8.row.col.f32.tf32.tf32.f32 "
                 "{%0,%1,%2,%3}, {%4,%5,%6,%7}, {%8,%9}, {%0,%1,%2,%3};"
                 : "+f"(c[0]), "+f"(c[1]), "+f"(c[2]), "+f"(c[3])
                 : "r"(a[0]), "r"(a[1]), "r"(a[2]), "r"(a[3]),
                   "r"(b0), "r"(b1));
}

// ================= tensor-core GEMM (reg-staged pipeline) =================
// Tile 64x128, K chunks of 32, smem double-buffered, global loads staged in
// registers so LDG latency hides behind the MMA block.
// 256 threads, 8 warps (2m x 4n), warp tile 32x32.
#define GT_AS (64*36)
#define GT_BS (32*132)
#define GT_SMEM ((2*GT_AS + 2*GT_BS)*4)    /* 52224 bytes */

template<bool RELU, bool BIAS>
__global__ __launch_bounds__(256) void gemm_tc(
    const float* __restrict__ A, const float* __restrict__ W,
    const float* __restrict__ bias, float* __restrict__ C,
    int M, int N, int K)
{
    extern __shared__ float sm[];
    float* As = sm;
    float* Bs = sm + 2*GT_AS;
    const int tid = threadIdx.x;
    const int m0 = blockIdx.y * 64, n0 = blockIdx.x * 128;

    const int lane = tid & 31, wid = tid >> 5;
    const int g = lane >> 2, tig = lane & 3;
    const int wm = wid & 1, wn = wid >> 1;
    const int warp_m0 = wm * 32, warp_n0 = wn * 32;

    // per-thread load coords
    const int ar = tid >> 3,        akq = (tid & 7) << 2;     // A: i=tid,tid+256
    const int ar2 = (tid + 256) >> 3, akq2 = ((tid + 256) & 7) << 2;

    float c[2][4][4];
    #pragma unroll
    for (int mi = 0; mi < 2; ++mi)
        #pragma unroll
        for (int nf = 0; nf < 4; ++nf)
            #pragma unroll
            for (int j = 0; j < 4; ++j) c[mi][nf][j] = 0.f;

    float4 ra0, ra1, rb[4];

    auto ldg_chunk = [&](int k0) {
        ra0 = *(const float4*)(A + (size_t)(m0 + ar)  * K + k0 + akq);
        ra1 = *(const float4*)(A + (size_t)(m0 + ar2) * K + k0 + akq2);
        #pragma unroll
        for (int ii = 0; ii < 4; ++ii) {
            int i = tid + ii * 256;
            int kk = i >> 5, nq = (i & 31) << 2;
            rb[ii] = *(const float4*)(W + (size_t)(k0 + kk) * N + n0 + nq);
        }
    };
    auto sts_chunk = [&](int bsel) {
        float* as = As + bsel * GT_AS;
        float* bs = Bs + bsel * GT_BS;
        *(float4*)&as[ar  * 36 + akq]  = cvt4(ra0);
        *(float4*)&as[ar2 * 36 + akq2] = cvt4(ra1);
        #pragma unroll
        for (int ii = 0; ii < 4; ++ii) {
            int i = tid + ii * 256;
            int kk = i >> 5, nq = (i & 31) << 2;
            *(float4*)&bs[kk * 132 + nq] = cvt4(rb[ii]);
        }
    };
    auto mma_chunk = [&](int bsel) {
        const float* as = As + bsel * GT_AS;
        const float* bs = Bs + bsel * GT_BS;
        #pragma unroll
        for (int ks = 0; ks < 4; ++ks) {
            const int kk = ks * 8;
            uint32_t a[2][4];
            #pragma unroll
            for (int mi = 0; mi < 2; ++mi) {
                int r0 = warp_m0 + mi * 16;
                a[mi][0] = __float_as_uint(as[(r0 + g)     * 36 + kk + tig]);
                a[mi][1] = __float_as_uint(as[(r0 + 8 + g) * 36 + kk + tig]);
                a[mi][2] = __float_as_uint(as[(r0 + g)     * 36 + kk + tig + 4]);
                a[mi][3] = __float_as_uint(as[(r0 + 8 + g) * 36 + kk + tig + 4]);
            }
            #pragma unroll
            for (int nf = 0; nf < 4; ++nf) {
                int cc = warp_n0 + nf * 8 + g;
                uint32_t b0 = __float_as_uint(bs[(kk + tig)     * 132 + cc]);
                uint32_t b1 = __float_as_uint(bs[(kk + tig + 4) * 132 + cc]);
                mma_tf32(c[0][nf], a[0], b0, b1);
                mma_tf32(c[1][nf], a[1], b0, b1);
            }
        }
    };

    ldg_chunk(0);
    sts_chunk(0);
    __syncthreads();
    const int nch = K >> 5;
    for (int gch = 0; gch < nch; ++gch) {
        if (gch + 1 < nch) ldg_chunk((gch + 1) << 5);
        mma_chunk(gch & 1);
        if (gch + 1 < nch) sts_chunk((gch + 1) & 1);
        __syncthreads();
    }

    #pragma unroll
    for (int mi = 0; mi < 2; ++mi) {
        #pragma unroll
        for (int nf = 0; nf < 4; ++nf) {
            int r0 = m0 + warp_m0 + mi * 16 + g;
            int cc = n0 + warp_n0 + nf * 8 + tig * 2;
            float o0 = c[mi][nf][0], o1 = c[mi][nf][1];
            float o2 = c[mi][nf][2], o3 = c[mi][nf][3];
            if (BIAS) {
                float bb0 = bias[cc], bb1 = bias[cc + 1];
                o0 += bb0; o1 += bb1; o2 += bb0; o3 += bb1;
            }
            if (RELU) {
                o0 = fmaxf(o0, 0.f); o1 = fmaxf(o1, 0.f);
                o2 = fmaxf(o2, 0.f); o3 = fmaxf(o3, 0.f);
            }
            *(float2*)(C + (size_t)r0 * N + cc)       = make_float2(o0, o1);
            *(float2*)(C + (size_t)(r0 + 8) * N + cc) = make_float2(o2, o3);
        }
    }
}

// ================= fused attention v4 (pipelined B) =================
// One CTA: 64 rows (TPB t's x Lp l-slots) x ALL 512 cols.
// A = tf32(tanh(v+henc)) built ONCE into persistent smem (64x516),
// then 4 n-passes of 128 cols with reg-staged, double-buffered B chunks.
#define AT_A  0                     /* 64*516 = 33024 floats */
#define AT_B  33024                 /* 2*32*132 = 8448 */
#define AT_R  41472                 /* 64*132  = 8448 */
#define AT_VT 49920                 /* 4*512   = 2048 */
#define AT_SMEM ((49920 + 2048) * 4)   /* 207872 bytes */

__global__ __launch_bounds__(256, 1) void attn_v4(
    const float* __restrict__ Wa, const float* __restrict__ word,
    const int* __restrict__ flen, const int* __restrict__ wlen,
    float* __restrict__ h2v_all, int write_h2v)
{
    extern __shared__ float sm[];
    const int tid = threadIdx.x;
    const int b  = blockIdx.y >> 8;
    const int yl = blockIdx.y & 255;
    const int fl = flen[b];

    int Lv = wlen[b]; if (Lv > LL) Lv = LL;
    const int lpsh = (Lv <= 16) ? 4 : (Lv <= 32) ? 5 : 6;
    const int lpmask = (1 << lpsh) - 1;
    const int TPB = 64 >> lpsh;                // 4 / 2 / 1
    const int t0 = yl * TPB;
    if (t0 >= TT) return;

    float* h2v = write_h2v ? h2v_all : nullptr;

    if (t0 >= fl) {       // fully masked t's: exact zeros
        float4 z = make_float4(0.f, 0.f, 0.f, 0.f);
        if (h2v) {
            for (int i = tid; i < TPB * LL * 128; i += 256) {
                int t = i / (LL * 128);
                int rem = i - t * (LL * 128);
                int l = rem >> 7, c4 = (rem & 127) << 2;
                *(float4*)&h2v[((size_t)(b * TT + t0 + t) * LL + l) * HD + c4] = z;
            }
        }
        for (int i = tid; i < TPB * 128; i += 256) {
            int t = i >> 7, c4 = (i & 127) << 2;
            *(float4*)&g_fww[(size_t)(b * TT + t0 + t) * HD + c4] = z;
        }
        return;
    }

    float* Am = sm + AT_A;
    float* Bb = sm + AT_B;
    float* R  = sm + AT_R;
    float* vt = sm + AT_VT;

    // stage v rows
    for (int i = tid; i < TPB * 128; i += 256) {
        int tl = i >> 7, c4 = (i & 127) << 2;
        *(float4*)&vt[tl * 512 + c4] =
            *(const float4*)&g_v[(size_t)(b * TT + t0 + tl) * HD + c4];
    }
    __syncthreads();

    // build A ONCE: tanh(v + henc) -> tf32, rows (t,l), zero padded l
    for (int i = tid; i < 64 * 128; i += 256) {
        int r = i >> 7, c4 = (i & 127) << 2;
        int tl = r >> lpsh, l = r & lpmask;
        float4 val = make_float4(0.f, 0.f, 0.f, 0.f);
        if (l < Lv) {
            float4 hv = *(const float4*)&g_henc[(size_t)(b * LL + l) * HD + c4];
            const float* vp = &vt[tl * 512 + c4];
            val.x = to_tf32(tanh_fast(vp[0] + hv.x));
            val.y = to_tf32(tanh_fast(vp[1] + hv.y));
            val.z = to_tf32(tanh_fast(vp[2] + hv.z));
            val.w = to_tf32(tanh_fast(vp[3] + hv.w));
        }
        *(float4*)&Am[r * 516 + c4] = val;
    }
    __syncthreads();

    const int lane = tid & 31, wid = tid >> 5;
    const int g = lane >> 2, tig = lane & 3;
    const int wm = wid & 1, wn = wid >> 1;      // 2m x 4n warp grid
    const int warp_m0 = wm * 32, warp_n0 = wn * 32;

    // B per-thread coords: 4 float4 per thread over 32x128
    const int bkk0 = tid >> 5, bnq0 = (tid & 31) << 2;

    for (int pass = 0; pass < 4; ++pass) {
        const int n0p = pass * 128;

        float c[2][4][4];
        #pragma unroll
        for (int mi = 0; mi < 2; ++mi)
            #pragma unroll
            for (int nf = 0; nf < 4; ++nf)
                #pragma unroll
                for (int j = 0; j < 4; ++j) c[mi][nf][j] = 0.f;

        float4 rb[4];
        auto ldgB = [&](int gch) {
            const int k0 = gch << 5;
            #pragma unroll
            for (int ii = 0; ii < 4; ++ii)
                rb[ii] = *(const float4*)&Wa[(size_t)(k0 + bkk0 + ii * 8) * HD + n0p + bnq0];
        };
        auto stsB = [&](int bsel) {
            float* bs = Bb + bsel * (32 * 132);
            #pragma unroll
            for (int ii = 0; ii < 4; ++ii)
                *(float4*)&bs[(bkk0 + ii * 8) * 132 + bnq0] = cvt4(rb[ii]);
        };

        ldgB(0);
        stsB(0);
        __syncthreads();
        for (int gch = 0; gch < 16; ++gch) {
            if (gch < 15) ldgB(gch + 1);
            {   // MMA over chunk gch: A from Am at kof, B from Bb[gch&1]
                const float* bs = Bb + (gch & 1) * (32 * 132);
                const int kof = gch << 5;
                #pragma unroll
                for (int ks = 0; ks < 4; ++ks) {
                    const int kk = kof + ks * 8;
                    uint32_t a[2][4];
                    #pragma unroll
                    for (int mi = 0; mi < 2; ++mi) {
                        int r0 = warp_m0 + mi * 16;
                        a[mi][0] = __float_as_uint(Am[(r0 + g)     * 516 + kk + tig]);
                        a[mi][1] = __float_as_uint(Am[(r0 + 8 + g) * 516 + kk + tig]);
                        a[mi][2] = __float_as_uint(Am[(r0 + g)     * 516 + kk + tig + 4]);
                        a[mi][3] = __float_as_uint(Am[(r0 + 8 + g) * 516 + kk + tig + 4]);
                    }
                    const int kl = ks * 8;
                    #pragma unroll
                    for (int nf = 0; nf < 4; ++nf) {
                        int cc = warp_n0 + nf * 8 + g;
                        uint32_t b0 = __float_as_uint(bs[(kl + tig)     * 132 + cc]);
                        uint32_t b1 = __float_as_uint(bs[(kl + tig + 4) * 132 + cc]);
                        mma_tf32(c[0][nf], a[0], b0, b1);
                        mma_tf32(c[1][nf], a[1], b0, b1);
                    }
                }
            }
            if (gch < 15) stsB((gch + 1) & 1);
            __syncthreads();
        }

        // relu(C) -> R [64][132]
        #pragma unroll
        for (int mi = 0; mi < 2; ++mi) {
            #pragma unroll
            for (int nf = 0; nf < 4; ++nf) {
                int rr0 = warp_m0 + mi * 16 + g;
                int cc  = warp_n0 + nf * 8 + tig * 2;
                *(float2*)&R[rr0 * 132 + cc] =
                    make_float2(fmaxf(c[mi][nf][0], 0.f), fmaxf(c[mi][nf][1], 0.f));
                *(float2*)&R[(rr0 + 8) * 132 + cc] =
                    make_float2(fmaxf(c[mi][nf][2], 0.f), fmaxf(c[mi][nf][3], 0.f));
            }
        }
        __syncthreads();

        // softmax over l + h2v + fww for cols [n0p, n0p+128)
        const int col = tid & 127;
        const int half = tid >> 7;
        for (int tg = half; tg < TPB; tg += 2) {
            const int t = t0 + tg;
            const int rb2 = tg << lpsh;
            const int hg = n0p + col;
            float* hp = h2v ? (h2v + ((size_t)(b * TT + t) * LL) * HD + hg) : nullptr;
            if (t < fl) {
                float mx = 0.f;
                for (int l = 0; l < Lv; ++l)
                    mx = fmaxf(mx, R[(rb2 + l) * 132 + col]);
                float sum = 0.f;
                for (int l = 0; l < Lv; ++l) {
                    float e = __expf(R[(rb2 + l) * 132 + col] - mx);
                    R[(rb2 + l) * 132 + col] = e;
                    sum += e;
                }
                float inv = 1.0f / sum;
                const float* wp = word + ((size_t)b * LL) * WDIM + hg;
                float fww = 0.f;
                for (int l = 0; l < Lv; ++l) {
                    float w = R[(rb2 + l) * 132 + col] * inv;
                    if (hp) hp[(size_t)l * HD] = w;
                    fww += w * wp[(size_t)l * WDIM];
                }
                if (hp)
                    for (int l = Lv; l < LL; ++l) hp[(size_t)l * HD] = 0.f;
                g_fww[(size_t)(b * TT + t) * HD + hg] = fww;
            } else {
                if (hp)
                    for (int l = 0; l < LL; ++l) hp[(size_t)l * HD] = 0.f;
                g_fww[(size_t)(b * TT + t) * HD + hg] = 0.f;
            }
        }
        __syncthreads();
    }
}

// ---------------- launcher ----------------
extern "C" void kernel_launch(void* const* d_in, const int* in_sizes, int n_in,
                              void* d_out, int out_size) {
    const float* frame = (const float*)d_in[0];
    const float* word  = (const float*)d_in[1];
    const int*   flen  = (const int*)  d_in[2];
    const int*   wlen  = (const int*)  d_in[3];
    const float* Wf    = (const float*)d_in[4];
    const float* bf    = (const float*)d_in[5];
    const float* Ww    = (const float*)d_in[6];
    const float* bw    = (const float*)d_in[7];
    const float* Wa    = (const float*)d_in[8];
    const float* Wout  = (const float*)d_in[9];
    float* out = (float*)d_out;

    float *henc, *v, *fww;
    cudaGetSymbolAddress((void**)&henc, g_henc);
    cudaGetSymbolAddress((void**)&v,    g_v);
    cudaGetSymbolAddress((void**)&fww,  g_fww);

    cudaFuncSetAttribute(gemm_tc<true, true>,
                         cudaFuncAttributeMaxDynamicSharedMemorySize, GT_SMEM);
    cudaFuncSetAttribute(gemm_tc<false, false>,
                         cudaFuncAttributeMaxDynamicSharedMemorySize, GT_SMEM);
    cudaFuncSetAttribute(attn_v4,
                         cudaFuncAttributeMaxDynamicSharedMemorySize, AT_SMEM);

    // 1) word encoder: henc = relu(word @ Ww + bw)   [384,512] K=512
    gemm_tc<true, true><<<dim3(HD / 128, (BB * LL) / 64), 256, GT_SMEM>>>(
        word, Ww, bw, henc, BB * LL, HD, WDIM);

    // 2) frame encoder: v = relu(frame @ Wf + bf)    [2048,512] K=1024
    gemm_tc<true, true><<<dim3(HD / 128, (BB * TT) / 64), 256, GT_SMEM>>>(
        frame, Wf, bf, v, BB * TT, HD, FDIM);

    // 3) fused attention (mma.sync tf32, A built once, B pipelined)
    int write_h2v = (out_size >= OUT_OFF + H2V_ELEMS) ? 1 : 0;
    attn_v4<<<dim3(1, BB * 256), 256, AT_SMEM>>>(
        Wa, word, flen, wlen, out + OUT_OFF, write_h2v);

    // 4) out = fww @ Wout    [2048,512] K=512
    gemm_tc<false, false><<<dim3(OD / 128, (BB * TT) / 64), 256, GT_SMEM>>>(
        fww, Wout, nullptr, out, BB * TT, OD, HD);
}